// round 1
// baseline (speedup 1.0000x reference)
#include <cuda_runtime.h>
#include <cuda_fp16.h>

#define Bsz 128
#define Nn  1024
#define Mm  1024
#define INV_EPS 20.0f      // 1/0.05
#define STAB 1e-8f
#define NUM_ITERS 10

// Scratch (allocation-free rule: __device__ globals)
__device__ __half d_K[(size_t)Bsz * Nn * Mm];   // 256 MB fp16 kernel matrix
__device__ float  d_u[Bsz * Nn];
__device__ float  d_v[Bsz * Mm];

// ---------------------------------------------------------------------------
// Pass 1: K = exp(-C/eps) in fp16, vectorized float4 -> 4x half
// ---------------------------------------------------------------------------
__global__ __launch_bounds__(256) void k_exp(const float* __restrict__ C) {
    size_t n4 = (size_t)Bsz * Nn * Mm / 4;
    size_t stride = (size_t)gridDim.x * blockDim.x;
    for (size_t i = (size_t)blockIdx.x * blockDim.x + threadIdx.x; i < n4; i += stride) {
        float4 c = reinterpret_cast<const float4*>(C)[i];
        __half2 lo = __floats2half2_rn(expf(-c.x * INV_EPS), expf(-c.y * INV_EPS));
        __half2 hi = __floats2half2_rn(expf(-c.z * INV_EPS), expf(-c.w * INV_EPS));
        union { __half2 h[2]; uint2 u; } p;
        p.h[0] = lo; p.h[1] = hi;
        reinterpret_cast<uint2*>(d_K)[i] = p.u;
    }
}

// init v = 1/M  (u is derived from v on the first half-iteration)
__global__ __launch_bounds__(256) void k_init() {
    int i = blockIdx.x * blockDim.x + threadIdx.x;
    if (i < Bsz * Mm) d_v[i] = 1.0f / (float)Mm;
}

// ---------------------------------------------------------------------------
// u[b,n] = 1 / (sum_m K[b,n,m] * v[b,m] + eps)   — warp per row
// ---------------------------------------------------------------------------
__global__ __launch_bounds__(256) void k_u() {
    int gwarp = (blockIdx.x * blockDim.x + threadIdx.x) >> 5;   // [0, B*N)
    int lane  = threadIdx.x & 31;
    int b     = gwarp >> 10;
    const __half* Krow = d_K + (size_t)gwarp * Mm;
    const float*  v    = d_v + b * Mm;

    float acc = 0.0f;
#pragma unroll
    for (int j = 0; j < 4; j++) {
        int base = j * 256 + lane * 8;                // 8 halves per lane per step
        uint4 kv = *reinterpret_cast<const uint4*>(Krow + base);
        float4 v0 = *reinterpret_cast<const float4*>(v + base);
        float4 v1 = *reinterpret_cast<const float4*>(v + base + 4);
        union { uint4 u; __half2 h[4]; } p; p.u = kv;
        float2 f0 = __half22float2(p.h[0]);
        float2 f1 = __half22float2(p.h[1]);
        float2 f2 = __half22float2(p.h[2]);
        float2 f3 = __half22float2(p.h[3]);
        acc += f0.x * v0.x + f0.y * v0.y + f1.x * v0.z + f1.y * v0.w
             + f2.x * v1.x + f2.y * v1.y + f3.x * v1.z + f3.y * v1.w;
    }
#pragma unroll
    for (int o = 16; o > 0; o >>= 1) acc += __shfl_xor_sync(0xFFFFFFFFu, acc, o);
    if (lane == 0) d_u[gwarp] = 1.0f / (acc + STAB);
}

// ---------------------------------------------------------------------------
// v[b,m] = 1 / (sum_n K[b,n,m] * u[b,n] + eps)
// block = 128 threads, each owns one half2 column pair (256 cols / block),
// grid = B * (M/256).  Consecutive threads -> consecutive m: coalesced.
// ---------------------------------------------------------------------------
__global__ __launch_bounds__(128) void k_v() {
    __shared__ float su[Nn];
    int b  = blockIdx.x >> 2;            // M/256 = 4 tiles per batch
    int c0 = (blockIdx.x & 3) * 256;
    const float* u = d_u + b * Nn;
    for (int i = threadIdx.x; i < Nn; i += 128) su[i] = u[i];
    __syncthreads();

    int m = c0 + threadIdx.x * 2;
    const __half2* Kc = reinterpret_cast<const __half2*>(d_K + (size_t)b * Nn * Mm + m);
    float2 accA = make_float2(0.f, 0.f);
    float2 accB = make_float2(0.f, 0.f);   // split chains: even/odd n
#pragma unroll 8
    for (int n = 0; n < Nn; n += 2) {
        float2 k0 = __half22float2(Kc[(size_t)n * (Mm / 2)]);
        float2 k1 = __half22float2(Kc[(size_t)(n + 1) * (Mm / 2)]);
        float u0 = su[n], u1 = su[n + 1];
        accA.x += k0.x * u0; accA.y += k0.y * u0;
        accB.x += k1.x * u1; accB.y += k1.y * u1;
    }
    d_v[b * Mm + m]     = 1.0f / (accA.x + accB.x + STAB);
    d_v[b * Mm + m + 1] = 1.0f / (accA.y + accB.y + STAB);
}

// ---------------------------------------------------------------------------
// out = u[:,None] * exp(-C/eps) * v[None,:]   — fp32-exact K for the output
// ---------------------------------------------------------------------------
__global__ __launch_bounds__(256) void k_out(const float* __restrict__ C,
                                             float* __restrict__ out) {
    size_t n4 = (size_t)Bsz * Nn * Mm / 4;
    size_t stride = (size_t)gridDim.x * blockDim.x;
    for (size_t i = (size_t)blockIdx.x * blockDim.x + threadIdx.x; i < n4; i += stride) {
        size_t e   = i * 4;
        int    m   = (int)(e & (Mm - 1));
        size_t row = e >> 10;          // b*N + n
        int    b   = (int)(row >> 10);
        float  un  = d_u[row];
        float4 c   = reinterpret_cast<const float4*>(C)[i];
        float4 vv  = *reinterpret_cast<const float4*>(d_v + b * Mm + m);
        float4 o;
        o.x = un * expf(-c.x * INV_EPS) * vv.x;
        o.y = un * expf(-c.y * INV_EPS) * vv.y;
        o.z = un * expf(-c.z * INV_EPS) * vv.z;
        o.w = un * expf(-c.w * INV_EPS) * vv.w;
        reinterpret_cast<float4*>(out)[i] = o;
    }
}

extern "C" void kernel_launch(void* const* d_in, const int* in_sizes, int n_in,
                              void* d_out, int out_size) {
    const float* C   = (const float*)d_in[0];
    float*       out = (float*)d_out;

    k_exp<<<8192, 256>>>(C);
    k_init<<<(Bsz * Mm + 255) / 256, 256>>>();
    for (int it = 0; it < NUM_ITERS; it++) {
        k_u<<<(Bsz * Nn) / 8, 256>>>();        // 8 warps/block, warp per row
        k_v<<<Bsz * 4, 128>>>();               // 256 cols per block
    }
    k_out<<<8192, 256>>>(C, out);
}

// round 2
// speedup vs baseline: 1.2125x; 1.2125x over previous
#include <cuda_runtime.h>
#include <cuda_fp16.h>

#define Bsz 128
#define Nn  1024
#define Mm  1024
#define NTILES 8              // row tiles per batch (128 rows each)
#define TROWS  128
#define INV_EPS 20.0f         // 1/0.05
#define STAB 1e-8f
#define NUM_ITERS 10

// Scratch (allocation-free rule: __device__ globals)
__device__ __half d_K[(size_t)Bsz * Nn * Mm];            // 256 MB fp16 kernel matrix
__device__ float  d_u[Bsz * Nn];
__device__ float  d_v[Bsz * Mm];
__device__ float  d_part[(size_t)NTILES * Bsz * Mm];     // 4 MB per-tile column partials

// ---------------------------------------------------------------------------
// Pass 1: K = exp(-C/eps) in fp16, vectorized float4 -> 4x half
// ---------------------------------------------------------------------------
__global__ __launch_bounds__(256) void k_exp(const float* __restrict__ C) {
    size_t n4 = (size_t)Bsz * Nn * Mm / 4;
    size_t stride = (size_t)gridDim.x * blockDim.x;
    for (size_t i = (size_t)blockIdx.x * blockDim.x + threadIdx.x; i < n4; i += stride) {
        float4 c = reinterpret_cast<const float4*>(C)[i];
        __half2 lo = __floats2half2_rn(__expf(-c.x * INV_EPS), __expf(-c.y * INV_EPS));
        __half2 hi = __floats2half2_rn(__expf(-c.z * INV_EPS), __expf(-c.w * INV_EPS));
        union { __half2 h[2]; uint2 u; } p;
        p.h[0] = lo; p.h[1] = hi;
        reinterpret_cast<uint2*>(d_K)[i] = p.u;
    }
}

__global__ __launch_bounds__(256) void k_init() {
    int i = blockIdx.x * blockDim.x + threadIdx.x;
    if (i < Bsz * Mm) d_v[i] = 1.0f / (float)Mm;
}

// ---------------------------------------------------------------------------
// Fused iteration kernel: block = (tile, batch), 256 threads.
// Phase 1: warp-per-row, u_new[r] = 1/(K[r,:]·v + eps) for the 128-row tile.
// Phase 2: thread-per-column-pair, partial[m] = sum_r K[r,m]*u_new[r]
//          (tile re-read served from L2), stored to d_part[tile] — no atomics.
// ---------------------------------------------------------------------------
__global__ __launch_bounds__(256) void k_fused() {
    __shared__ float sv[Mm];
    __shared__ float su[TROWS];
    int tile = blockIdx.x;          // 0..7
    int b    = blockIdx.y;          // 0..127

    const float* v = d_v + b * Mm;
    for (int i = threadIdx.x; i < Mm; i += 256) sv[i] = v[i];
    __syncthreads();

    int warp = threadIdx.x >> 5;
    int lane = threadIdx.x & 31;
    const __half* Ktile = d_K + ((size_t)b * Nn + tile * TROWS) * Mm;

    // ---- Phase 1: row dots -> u_new ----
    for (int r = warp; r < TROWS; r += 8) {
        const __half* Krow = Ktile + (size_t)r * Mm;
        float acc = 0.0f;
#pragma unroll
        for (int j = 0; j < 4; j++) {
            int base = j * 256 + lane * 8;
            uint4 kv = *reinterpret_cast<const uint4*>(Krow + base);
            float4 v0 = *reinterpret_cast<const float4*>(sv + base);
            float4 v1 = *reinterpret_cast<const float4*>(sv + base + 4);
            union { uint4 u; __half2 h[4]; } p; p.u = kv;
            float2 f0 = __half22float2(p.h[0]);
            float2 f1 = __half22float2(p.h[1]);
            float2 f2 = __half22float2(p.h[2]);
            float2 f3 = __half22float2(p.h[3]);
            acc += f0.x * v0.x + f0.y * v0.y + f1.x * v0.z + f1.y * v0.w
                 + f2.x * v1.x + f2.y * v1.y + f3.x * v1.z + f3.y * v1.w;
        }
#pragma unroll
        for (int o = 16; o > 0; o >>= 1) acc += __shfl_xor_sync(0xFFFFFFFFu, acc, o);
        if (lane == 0) {
            float un = 1.0f / (acc + STAB);
            su[r] = un;
            d_u[b * Nn + tile * TROWS + r] = un;
        }
    }
    __syncthreads();

    // ---- Phase 2: column partial sums with new u (tile hot in L2) ----
    const __half2* Kt = reinterpret_cast<const __half2*>(Ktile);
    int c0 = threadIdx.x;           // half2 column index [0,256)
    int c1 = threadIdx.x + 256;     // [256,512)
    float2 a0 = make_float2(0.f, 0.f);
    float2 a1 = make_float2(0.f, 0.f);
#pragma unroll 4
    for (int n = 0; n < TROWS; n++) {
        float un = su[n];
        float2 k0 = __half22float2(Kt[(size_t)n * (Mm / 2) + c0]);
        float2 k1 = __half22float2(Kt[(size_t)n * (Mm / 2) + c1]);
        a0.x += k0.x * un; a0.y += k0.y * un;
        a1.x += k1.x * un; a1.y += k1.y * un;
    }
    float* P = d_part + (size_t)tile * (Bsz * Mm) + b * Mm;
    *reinterpret_cast<float2*>(P + 2 * c0) = a0;
    *reinterpret_cast<float2*>(P + 2 * c1) = a1;
}

// ---------------------------------------------------------------------------
// Finalize: v = 1 / (sum of 8 tile partials + eps)
// ---------------------------------------------------------------------------
__global__ __launch_bounds__(256) void k_fin() {
    int i = blockIdx.x * 256 + threadIdx.x;    // [0, B*M)
    float s = 0.0f;
#pragma unroll
    for (int t = 0; t < NTILES; t++) s += d_part[(size_t)t * (Bsz * Mm) + i];
    d_v[i] = 1.0f / (s + STAB);
}

// ---------------------------------------------------------------------------
// out = u[:,None] * exp(-C/eps) * v[None,:]   — fp32-exact K for the output
// ---------------------------------------------------------------------------
__global__ __launch_bounds__(256) void k_out(const float* __restrict__ C,
                                             float* __restrict__ out) {
    size_t n4 = (size_t)Bsz * Nn * Mm / 4;
    size_t stride = (size_t)gridDim.x * blockDim.x;
    for (size_t i = (size_t)blockIdx.x * blockDim.x + threadIdx.x; i < n4; i += stride) {
        size_t e   = i * 4;
        int    m   = (int)(e & (Mm - 1));
        size_t row = e >> 10;          // b*N + n
        int    b   = (int)(row >> 10);
        float  un  = d_u[row];
        float4 c   = reinterpret_cast<const float4*>(C)[i];
        float4 vv  = *reinterpret_cast<const float4*>(d_v + b * Mm + m);
        float4 o;
        o.x = un * __expf(-c.x * INV_EPS) * vv.x;
        o.y = un * __expf(-c.y * INV_EPS) * vv.y;
        o.z = un * __expf(-c.z * INV_EPS) * vv.z;
        o.w = un * __expf(-c.w * INV_EPS) * vv.w;
        reinterpret_cast<float4*>(out)[i] = o;
    }
}

extern "C" void kernel_launch(void* const* d_in, const int* in_sizes, int n_in,
                              void* d_out, int out_size) {
    const float* C   = (const float*)d_in[0];
    float*       out = (float*)d_out;

    k_exp<<<8192, 256>>>(C);
    k_init<<<(Bsz * Mm + 255) / 256, 256>>>();
    dim3 grid(NTILES, Bsz);
    for (int it = 0; it < NUM_ITERS; it++) {
        k_fused<<<grid, 256>>>();
        k_fin<<<(Bsz * Mm) / 256, 256>>>();
    }
    k_out<<<8192, 256>>>(C, out);
}

// round 3
// speedup vs baseline: 1.2184x; 1.0049x over previous
#include <cuda_runtime.h>
#include <cuda_fp16.h>

#define Bsz 128
#define Nn  1024
#define Mm  1024
#define TROWS  32              // rows per tile (64 KB fp16 in smem)
#define NTILES 32              // 1024 / 32
#define INV_EPS 20.0f          // 1/0.05
#define STAB 1e-8f
#define NUM_ITERS 10

// Scratch (allocation-free rule: __device__ globals)
__device__ __half d_K[(size_t)Bsz * Nn * Mm];            // 256 MB fp16 kernel matrix
__device__ float  d_u[Bsz * Nn];
__device__ float  d_v[Bsz * Mm];
__device__ float  d_part[(size_t)NTILES * Bsz * Mm];     // 16 MB per-tile column partials

// ---------------------------------------------------------------------------
// Pass 1: K = exp(-C/eps) in fp16
// ---------------------------------------------------------------------------
__global__ __launch_bounds__(256) void k_exp(const float* __restrict__ C) {
    size_t n4 = (size_t)Bsz * Nn * Mm / 4;
    size_t stride = (size_t)gridDim.x * blockDim.x;
    for (size_t i = (size_t)blockIdx.x * blockDim.x + threadIdx.x; i < n4; i += stride) {
        float4 c = reinterpret_cast<const float4*>(C)[i];
        __half2 lo = __floats2half2_rn(__expf(-c.x * INV_EPS), __expf(-c.y * INV_EPS));
        __half2 hi = __floats2half2_rn(__expf(-c.z * INV_EPS), __expf(-c.w * INV_EPS));
        union { __half2 h[2]; uint2 u; } p;
        p.h[0] = lo; p.h[1] = hi;
        reinterpret_cast<uint2*>(d_K)[i] = p.u;
    }
}

__global__ __launch_bounds__(256) void k_init() {
    int i = blockIdx.x * blockDim.x + threadIdx.x;
    if (i < Bsz * Mm) d_v[i] = 1.0f / (float)Mm;
}

// ---------------------------------------------------------------------------
// Fused iteration: block = (tile, batch), 256 threads, tile cached in SMEM.
// Phase 1: warp-per-row — load row from DRAM once, stash in smem, dot with v.
// Phase 2: thread-per-column-pair over the SMEM tile with the new u.
// ---------------------------------------------------------------------------
__global__ __launch_bounds__(256) void k_fused() {
    extern __shared__ char smem[];
    __half* tile = reinterpret_cast<__half*>(smem);              // [TROWS*Mm]  64 KB
    float*  sv   = reinterpret_cast<float*>(smem + TROWS * Mm * 2); // [Mm] 4 KB
    float*  su   = sv + Mm;                                      // [TROWS]

    int t = blockIdx.x;             // 0..31
    int b = blockIdx.y;             // 0..127

    const float* v = d_v + b * Mm;
    for (int i = threadIdx.x; i < Mm; i += 256) sv[i] = v[i];
    __syncthreads();

    int warp = threadIdx.x >> 5;
    int lane = threadIdx.x & 31;
    const __half* Ktile = d_K + ((size_t)b * Nn + t * TROWS) * Mm;

    // ---- Phase 1: row dots -> u_new, tile -> smem ----
#pragma unroll
    for (int rr = 0; rr < 4; rr++) {
        int r = warp * 4 + rr;
        const __half* Krow = Ktile + (size_t)r * Mm;
        __half*       Srow = tile + r * Mm;
        float acc = 0.0f;
#pragma unroll
        for (int j = 0; j < 4; j++) {
            int base = j * 256 + lane * 8;
            uint4 kv = *reinterpret_cast<const uint4*>(Krow + base);
            *reinterpret_cast<uint4*>(Srow + base) = kv;
            float4 v0 = *reinterpret_cast<const float4*>(sv + base);
            float4 v1 = *reinterpret_cast<const float4*>(sv + base + 4);
            union { uint4 u; __half2 h[4]; } p; p.u = kv;
            float2 f0 = __half22float2(p.h[0]);
            float2 f1 = __half22float2(p.h[1]);
            float2 f2 = __half22float2(p.h[2]);
            float2 f3 = __half22float2(p.h[3]);
            acc += f0.x * v0.x + f0.y * v0.y + f1.x * v0.z + f1.y * v0.w
                 + f2.x * v1.x + f2.y * v1.y + f3.x * v1.z + f3.y * v1.w;
        }
#pragma unroll
        for (int o = 16; o > 0; o >>= 1) acc += __shfl_xor_sync(0xFFFFFFFFu, acc, o);
        if (lane == 0) {
            float un = 1.0f / (acc + STAB);
            su[r] = un;
            d_u[b * Nn + t * TROWS + r] = un;
        }
    }
    __syncthreads();

    // ---- Phase 2: column partials from SMEM tile ----
    const __half2* T2 = reinterpret_cast<const __half2*>(tile);
    int c0 = threadIdx.x;          // half2 col [0,256)
    int c1 = threadIdx.x + 256;    // [256,512)
    float2 a0 = make_float2(0.f, 0.f);
    float2 a1 = make_float2(0.f, 0.f);
#pragma unroll 8
    for (int n = 0; n < TROWS; n++) {
        float un = su[n];
        float2 k0 = __half22float2(T2[n * (Mm / 2) + c0]);
        float2 k1 = __half22float2(T2[n * (Mm / 2) + c1]);
        a0.x += k0.x * un; a0.y += k0.y * un;
        a1.x += k1.x * un; a1.y += k1.y * un;
    }
    float* P = d_part + (size_t)t * (Bsz * Mm) + b * Mm;
    *reinterpret_cast<float2*>(P + 2 * c0) = a0;
    *reinterpret_cast<float2*>(P + 2 * c1) = a1;
}

// ---------------------------------------------------------------------------
// Finalize: v = 1 / (sum of 32 tile partials + eps), float4-vectorized
// ---------------------------------------------------------------------------
__global__ __launch_bounds__(128) void k_fin() {
    int i4 = blockIdx.x * 128 + threadIdx.x;   // [0, B*M/4)
    float4 s = make_float4(0.f, 0.f, 0.f, 0.f);
#pragma unroll
    for (int t = 0; t < NTILES; t++) {
        float4 p = reinterpret_cast<const float4*>(d_part + (size_t)t * (Bsz * Mm))[i4];
        s.x += p.x; s.y += p.y; s.z += p.z; s.w += p.w;
    }
    float4 o;
    o.x = 1.0f / (s.x + STAB);
    o.y = 1.0f / (s.y + STAB);
    o.z = 1.0f / (s.z + STAB);
    o.w = 1.0f / (s.w + STAB);
    reinterpret_cast<float4*>(d_v)[i4] = o;
}

// ---------------------------------------------------------------------------
// out = u[:,None] * K * v[None,:]   — K read back in fp16 (no C re-read)
// ---------------------------------------------------------------------------
__global__ __launch_bounds__(256) void k_out(float* __restrict__ out) {
    size_t n4 = (size_t)Bsz * Nn * Mm / 4;
    size_t stride = (size_t)gridDim.x * blockDim.x;
    for (size_t i = (size_t)blockIdx.x * blockDim.x + threadIdx.x; i < n4; i += stride) {
        size_t e   = i * 4;
        int    m   = (int)(e & (Mm - 1));
        size_t row = e >> 10;          // b*N + n
        int    b   = (int)(row >> 10);
        float  un  = d_u[row];
        union { uint2 u; __half2 h[2]; } p;
        p.u = reinterpret_cast<const uint2*>(d_K)[i];
        float2 k0 = __half22float2(p.h[0]);
        float2 k1 = __half22float2(p.h[1]);
        float4 vv = *reinterpret_cast<const float4*>(d_v + b * Mm + m);
        float4 o;
        o.x = un * k0.x * vv.x;
        o.y = un * k0.y * vv.y;
        o.z = un * k1.x * vv.z;
        o.w = un * k1.y * vv.w;
        reinterpret_cast<float4*>(out)[i] = o;
    }
}

extern "C" void kernel_launch(void* const* d_in, const int* in_sizes, int n_in,
                              void* d_out, int out_size) {
    const float* C   = (const float*)d_in[0];
    float*       out = (float*)d_out;

    static const int SMEM_BYTES = TROWS * Mm * 2 + Mm * 4 + TROWS * 4 + 16;
    cudaFuncSetAttribute(k_fused, cudaFuncAttributeMaxDynamicSharedMemorySize, SMEM_BYTES);

    k_exp<<<8192, 256>>>(C);
    k_init<<<(Bsz * Mm + 255) / 256, 256>>>();
    dim3 grid(NTILES, Bsz);
    for (int it = 0; it < NUM_ITERS; it++) {
        k_fused<<<grid, 256, SMEM_BYTES>>>();
        k_fin<<<(Bsz * Mm) / (4 * 128), 128>>>();
    }
    k_out<<<8192, 256>>>(out);
}

// round 4
// speedup vs baseline: 1.4064x; 1.1543x over previous
#include <cuda_runtime.h>
#include <cuda_fp16.h>

#define Bsz 128
#define Nn  1024
#define Mm  1024
#define TROWS  64              // rows per tile; 8 warps x 8 rows
#define NTILES 16              // 1024 / 64
#define INV_EPS 20.0f          // 1/0.05
#define STAB 1e-8f
#define NUM_ITERS 10

// Scratch (allocation-free rule: __device__ globals)
__device__ __half d_K[(size_t)Bsz * Nn * Mm];            // 256 MB fp16 kernel matrix
__device__ float  d_u[Bsz * Nn];
__device__ float  d_v[Bsz * Mm];
__device__ float  d_part[(size_t)NTILES * Bsz * Mm];     // 8 MB per-tile column partials

// ---------------------------------------------------------------------------
// Pass 1: K = exp(-C/eps) in fp16
// ---------------------------------------------------------------------------
__global__ __launch_bounds__(256) void k_exp(const float* __restrict__ C) {
    size_t n4 = (size_t)Bsz * Nn * Mm / 4;
    size_t stride = (size_t)gridDim.x * blockDim.x;
    for (size_t i = (size_t)blockIdx.x * blockDim.x + threadIdx.x; i < n4; i += stride) {
        float4 c = reinterpret_cast<const float4*>(C)[i];
        __half2 lo = __floats2half2_rn(__expf(-c.x * INV_EPS), __expf(-c.y * INV_EPS));
        __half2 hi = __floats2half2_rn(__expf(-c.z * INV_EPS), __expf(-c.w * INV_EPS));
        union { __half2 h[2]; uint2 u; } p;
        p.h[0] = lo; p.h[1] = hi;
        reinterpret_cast<uint2*>(d_K)[i] = p.u;
    }
}

__global__ __launch_bounds__(256) void k_init() {
    int i = blockIdx.x * blockDim.x + threadIdx.x;
    if (i < Bsz * Mm) d_v[i] = 1.0f / (float)Mm;
}

// ---------------------------------------------------------------------------
// Fused iteration, single pass over K:
// warp processes 8 rows (in pairs for MLP). For each row pair:
//   - load both rows into registers (8 independent LDG.128 / lane)
//   - dot with v (smem), butterfly reduce -> every lane holds u_new
//   - immediately accumulate K[r,m]*u_new into 32 per-lane column accumulators
// End: 8-warp smem reduction of column partials -> d_part[tile].
// ---------------------------------------------------------------------------
__global__ __launch_bounds__(256) void k_fused() {
    __shared__ float sv[Mm];                 // 4 KB
    __shared__ float spart[8 * Mm];          // 32 KB

    int t = blockIdx.x;                      // tile 0..15
    int b = blockIdx.y;                      // batch 0..127
    int warp = threadIdx.x >> 5;
    int lane = threadIdx.x & 31;

    // stage v
    {
        const float4* v4 = reinterpret_cast<const float4*>(d_v + b * Mm);
        reinterpret_cast<float4*>(sv)[threadIdx.x] = v4[threadIdx.x];
    }
    __syncthreads();

    const __half* Ktile = d_K + ((size_t)b * Nn + t * TROWS) * Mm;

    float colacc[32];
#pragma unroll
    for (int i = 0; i < 32; i++) colacc[i] = 0.0f;

    int r0 = warp * 8;
#pragma unroll
    for (int rp = 0; rp < 4; rp++) {
        const __half* Krow0 = Ktile + (size_t)(r0 + 2 * rp) * Mm;
        const __half* Krow1 = Krow0 + Mm;
        uint4 kv0[4], kv1[4];
#pragma unroll
        for (int j = 0; j < 4; j++) {
            int base = j * 256 + lane * 8;
            kv0[j] = *reinterpret_cast<const uint4*>(Krow0 + base);
            kv1[j] = *reinterpret_cast<const uint4*>(Krow1 + base);
        }
        float acc0 = 0.0f, acc1 = 0.0f;
#pragma unroll
        for (int j = 0; j < 4; j++) {
            int base = j * 256 + lane * 8;
            float4 v0 = *reinterpret_cast<const float4*>(sv + base);
            float4 v1 = *reinterpret_cast<const float4*>(sv + base + 4);
            union { uint4 u; __half2 h[4]; } p;
            p.u = kv0[j];
            float2 a = __half22float2(p.h[0]);
            float2 bb = __half22float2(p.h[1]);
            float2 cc = __half22float2(p.h[2]);
            float2 dd = __half22float2(p.h[3]);
            acc0 += a.x * v0.x + a.y * v0.y + bb.x * v0.z + bb.y * v0.w
                  + cc.x * v1.x + cc.y * v1.y + dd.x * v1.z + dd.y * v1.w;
            p.u = kv1[j];
            a = __half22float2(p.h[0]); bb = __half22float2(p.h[1]);
            cc = __half22float2(p.h[2]); dd = __half22float2(p.h[3]);
            acc1 += a.x * v0.x + a.y * v0.y + bb.x * v0.z + bb.y * v0.w
                  + cc.x * v1.x + cc.y * v1.y + dd.x * v1.z + dd.y * v1.w;
        }
#pragma unroll
        for (int o = 16; o > 0; o >>= 1) {
            acc0 += __shfl_xor_sync(0xFFFFFFFFu, acc0, o);
            acc1 += __shfl_xor_sync(0xFFFFFFFFu, acc1, o);
        }
        float u0 = 1.0f / (acc0 + STAB);
        float u1 = 1.0f / (acc1 + STAB);
        if (lane == 0) {
            int gr = b * Nn + t * TROWS + r0 + 2 * rp;
            d_u[gr]     = u0;
            d_u[gr + 1] = u1;
        }
        // column accumulation from registers
#pragma unroll
        for (int j = 0; j < 4; j++) {
            union { uint4 u; __half2 h[4]; } p0, p1;
            p0.u = kv0[j]; p1.u = kv1[j];
#pragma unroll
            for (int q = 0; q < 4; q++) {
                float2 f0 = __half22float2(p0.h[q]);
                float2 f1 = __half22float2(p1.h[q]);
                colacc[j * 8 + 2 * q]     += f0.x * u0 + f1.x * u1;
                colacc[j * 8 + 2 * q + 1] += f0.y * u0 + f1.y * u1;
            }
        }
    }

    // per-warp partials -> smem
#pragma unroll
    for (int j = 0; j < 4; j++) {
        float* dst = spart + warp * Mm + j * 256 + lane * 8;
        *reinterpret_cast<float4*>(dst)     = make_float4(colacc[j*8+0], colacc[j*8+1], colacc[j*8+2], colacc[j*8+3]);
        *reinterpret_cast<float4*>(dst + 4) = make_float4(colacc[j*8+4], colacc[j*8+5], colacc[j*8+6], colacc[j*8+7]);
    }
    __syncthreads();

    // block reduce 8 warps -> d_part[tile]
    {
        int c = threadIdx.x * 4;
        float4 s = make_float4(0.f, 0.f, 0.f, 0.f);
#pragma unroll
        for (int w = 0; w < 8; w++) {
            float4 p = *reinterpret_cast<const float4*>(spart + w * Mm + c);
            s.x += p.x; s.y += p.y; s.z += p.z; s.w += p.w;
        }
        *reinterpret_cast<float4*>(d_part + (size_t)t * (Bsz * Mm) + b * Mm + c) = s;
    }
}

// ---------------------------------------------------------------------------
// Finalize: v = 1 / (sum of 16 tile partials + eps)
// ---------------------------------------------------------------------------
__global__ __launch_bounds__(256) void k_fin() {
    int i4 = blockIdx.x * 256 + threadIdx.x;   // [0, B*M/4)
    float4 s = make_float4(0.f, 0.f, 0.f, 0.f);
#pragma unroll
    for (int t = 0; t < NTILES; t++) {
        float4 p = reinterpret_cast<const float4*>(d_part + (size_t)t * (Bsz * Mm))[i4];
        s.x += p.x; s.y += p.y; s.z += p.z; s.w += p.w;
    }
    float4 o;
    o.x = 1.0f / (s.x + STAB);
    o.y = 1.0f / (s.y + STAB);
    o.z = 1.0f / (s.z + STAB);
    o.w = 1.0f / (s.w + STAB);
    reinterpret_cast<float4*>(d_v)[i4] = o;
}

// ---------------------------------------------------------------------------
// out = u[:,None] * K * v[None,:]   — K read back in fp16 (no C re-read)
// ---------------------------------------------------------------------------
__global__ __launch_bounds__(256) void k_out(float* __restrict__ out) {
    size_t n4 = (size_t)Bsz * Nn * Mm / 4;
    size_t stride = (size_t)gridDim.x * blockDim.x;
    for (size_t i = (size_t)blockIdx.x * blockDim.x + threadIdx.x; i < n4; i += stride) {
        size_t e   = i * 4;
        int    m   = (int)(e & (Mm - 1));
        size_t row = e >> 10;          // b*N + n
        int    b   = (int)(row >> 10);
        float  un  = d_u[row];
        union { uint2 u; __half2 h[2]; } p;
        p.u = reinterpret_cast<const uint2*>(d_K)[i];
        float2 k0 = __half22float2(p.h[0]);
        float2 k1 = __half22float2(p.h[1]);
        float4 vv = *reinterpret_cast<const float4*>(d_v + b * Mm + m);
        float4 o;
        o.x = un * k0.x * vv.x;
        o.y = un * k0.y * vv.y;
        o.z = un * k1.x * vv.z;
        o.w = un * k1.y * vv.w;
        reinterpret_cast<float4*>(out)[i] = o;
    }
}

extern "C" void kernel_launch(void* const* d_in, const int* in_sizes, int n_in,
                              void* d_out, int out_size) {
    const float* C   = (const float*)d_in[0];
    float*       out = (float*)d_out;

    k_exp<<<8192, 256>>>(C);
    k_init<<<(Bsz * Mm + 255) / 256, 256>>>();
    dim3 grid(NTILES, Bsz);
    for (int it = 0; it < NUM_ITERS; it++) {
        k_fused<<<grid, 256>>>();
        k_fin<<<(Bsz * Mm) / (4 * 256), 256>>>();
    }
    k_out<<<8192, 256>>>(out);
}

// round 6
// speedup vs baseline: 1.7014x; 1.2098x over previous
#include <cuda_runtime.h>
#include <cuda_fp16.h>

#define Bsz 128
#define Nn  1024
#define Mm  1024
#define TROWS  128             // rows per tile; 8 warps x 16 rows
#define NTILES 8               // 1024 / 128
#define INV_EPS 20.0f          // 1/0.05
#define STAB 1e-8f
#define NUM_ITERS 10

// Scratch (allocation-free rule: __device__ globals)
__device__ __half d_K[(size_t)Bsz * Nn * Mm];            // 256 MB fp16 kernel matrix
__device__ float  d_u[Bsz * Nn];
__device__ float  d_v[Bsz * Mm];
__device__ float  d_part[(size_t)NTILES * Bsz * Mm];     // 4 MB per-tile column partials

// ---------------------------------------------------------------------------
// Pass 1: K = exp(-C/eps) in fp16 (launched twice over half ranges so the
// ncu capture point -s 5 lands on k_fused)
// ---------------------------------------------------------------------------
__global__ __launch_bounds__(256) void k_exp(const float* __restrict__ C, size_t off4, size_t cnt4) {
    size_t stride = (size_t)gridDim.x * blockDim.x;
    for (size_t i = (size_t)blockIdx.x * blockDim.x + threadIdx.x; i < cnt4; i += stride) {
        size_t idx = off4 + i;
        float4 c = reinterpret_cast<const float4*>(C)[idx];
        __half2 lo = __floats2half2_rn(__expf(-c.x * INV_EPS), __expf(-c.y * INV_EPS));
        __half2 hi = __floats2half2_rn(__expf(-c.z * INV_EPS), __expf(-c.w * INV_EPS));
        union { __half2 h[2]; uint2 u; } p;
        p.h[0] = lo; p.h[1] = hi;
        reinterpret_cast<uint2*>(d_K)[idx] = p.u;
    }
}

__global__ __launch_bounds__(256) void k_init() {
    int i = blockIdx.x * blockDim.x + threadIdx.x;
    if (i < Bsz * Mm) d_v[i] = 1.0f / (float)Mm;
}

// ---------------------------------------------------------------------------
// Fused iteration, single pass over K, single fp16->fp32 convert per element:
// warp processes 16 rows. Per row: load 4x uint4, convert -> rowf[32],
// dot with vreg[32] (registers), butterfly reduce (all lanes get sum),
// u = 1/(sum+eps), colacc[32] += rowf * u. End: 8-warp smem reduction.
// ---------------------------------------------------------------------------
__global__ __launch_bounds__(256, 2) void k_fused() {
    __shared__ float spart[8 * Mm];          // 32 KB

    int t = blockIdx.x;                      // tile 0..7
    int b = blockIdx.y;                      // batch 0..127
    int warp = threadIdx.x >> 5;
    int lane = threadIdx.x & 31;

    // v for this lane's 32 fixed columns -> registers
    float vreg[32];
    {
        const float* v = d_v + b * Mm;
#pragma unroll
        for (int j = 0; j < 4; j++) {
            int base = j * 256 + lane * 8;
            float4 a0 = *reinterpret_cast<const float4*>(v + base);
            float4 a1 = *reinterpret_cast<const float4*>(v + base + 4);
            vreg[j*8+0] = a0.x; vreg[j*8+1] = a0.y; vreg[j*8+2] = a0.z; vreg[j*8+3] = a0.w;
            vreg[j*8+4] = a1.x; vreg[j*8+5] = a1.y; vreg[j*8+6] = a1.z; vreg[j*8+7] = a1.w;
        }
    }

    float colacc[32];
#pragma unroll
    for (int i = 0; i < 32; i++) colacc[i] = 0.0f;

    const __half* Ktile = d_K + ((size_t)b * Nn + t * TROWS) * Mm;

#pragma unroll 2
    for (int rr = 0; rr < 16; rr++) {
        int r = rr * 8 + warp;               // 8 warps sweep 8 consecutive rows
        const __half* Krow = Ktile + (size_t)r * Mm;

        float rowf[32];
#pragma unroll
        for (int j = 0; j < 4; j++) {
            uint4 kv = *reinterpret_cast<const uint4*>(Krow + j * 256 + lane * 8);
            union { uint4 u; __half2 h[4]; } p; p.u = kv;
#pragma unroll
            for (int q = 0; q < 4; q++) {
                float2 f = __half22float2(p.h[q]);
                rowf[j*8 + 2*q]     = f.x;
                rowf[j*8 + 2*q + 1] = f.y;
            }
        }

        float acc = 0.0f;
#pragma unroll
        for (int i = 0; i < 32; i++) acc += rowf[i] * vreg[i];
#pragma unroll
        for (int o = 16; o > 0; o >>= 1) acc += __shfl_xor_sync(0xFFFFFFFFu, acc, o);

        float u = 1.0f / (acc + STAB);
        if (lane == 0) d_u[b * Nn + t * TROWS + r] = u;

#pragma unroll
        for (int i = 0; i < 32; i++) colacc[i] += rowf[i] * u;
    }

    // per-warp partials -> smem
#pragma unroll
    for (int j = 0; j < 4; j++) {
        float* dst = spart + warp * Mm + j * 256 + lane * 8;
        *reinterpret_cast<float4*>(dst)     = make_float4(colacc[j*8+0], colacc[j*8+1], colacc[j*8+2], colacc[j*8+3]);
        *reinterpret_cast<float4*>(dst + 4) = make_float4(colacc[j*8+4], colacc[j*8+5], colacc[j*8+6], colacc[j*8+7]);
    }
    __syncthreads();

    // block reduce 8 warps -> d_part[tile]
    {
        int c = threadIdx.x * 4;
        float4 s = make_float4(0.f, 0.f, 0.f, 0.f);
#pragma unroll
        for (int w = 0; w < 8; w++) {
            float4 p = *reinterpret_cast<const float4*>(spart + w * Mm + c);
            s.x += p.x; s.y += p.y; s.z += p.z; s.w += p.w;
        }
        *reinterpret_cast<float4*>(d_part + (size_t)t * (Bsz * Mm) + b * Mm + c) = s;
    }
}

// ---------------------------------------------------------------------------
// Finalize: v = 1 / (sum of 8 tile partials + eps)
// ---------------------------------------------------------------------------
__global__ __launch_bounds__(256) void k_fin() {
    int i4 = blockIdx.x * 256 + threadIdx.x;   // [0, B*M/4)
    float4 s = make_float4(0.f, 0.f, 0.f, 0.f);
#pragma unroll
    for (int t = 0; t < NTILES; t++) {
        float4 p = reinterpret_cast<const float4*>(d_part + (size_t)t * (Bsz * Mm))[i4];
        s.x += p.x; s.y += p.y; s.z += p.z; s.w += p.w;
    }
    float4 o;
    o.x = 1.0f / (s.x + STAB);
    o.y = 1.0f / (s.y + STAB);
    o.z = 1.0f / (s.z + STAB);
    o.w = 1.0f / (s.w + STAB);
    reinterpret_cast<float4*>(d_v)[i4] = o;
}

// ---------------------------------------------------------------------------
// out = u[:,None] * K * v[None,:]   — K read back in fp16 (no C re-read)
// ---------------------------------------------------------------------------
__global__ __launch_bounds__(256) void k_out(float* __restrict__ out) {
    size_t n4 = (size_t)Bsz * Nn * Mm / 4;
    size_t stride = (size_t)gridDim.x * blockDim.x;
    for (size_t i = (size_t)blockIdx.x * blockDim.x + threadIdx.x; i < n4; i += stride) {
        size_t e   = i * 4;
        int    m   = (int)(e & (Mm - 1));
        size_t row = e >> 10;          // b*N + n
        int    b   = (int)(row >> 10);
        float  un  = d_u[row];
        union { uint2 u; __half2 h[2]; } p;
        p.u = reinterpret_cast<const uint2*>(d_K)[i];
        float2 k0 = __half22float2(p.h[0]);
        float2 k1 = __half22float2(p.h[1]);
        float4 vv = *reinterpret_cast<const float4*>(d_v + b * Mm + m);
        float4 o;
        o.x = un * k0.x * vv.x;
        o.y = un * k0.y * vv.y;
        o.z = un * k1.x * vv.z;
        o.w = un * k1.y * vv.w;
        reinterpret_cast<float4*>(out)[i] = o;
    }
}

extern "C" void kernel_launch(void* const* d_in, const int* in_sizes, int n_in,
                              void* d_out, int out_size) {
    const float* C   = (const float*)d_in[0];
    float*       out = (float*)d_out;

    size_t n4   = (size_t)Bsz * Nn * Mm / 4;
    size_t half = n4 / 2;
    k_exp<<<8192, 256>>>(C, 0, half);        // launch 1
    k_exp<<<8192, 256>>>(C, half, half);     // launch 2
    k_init<<<(Bsz * Mm + 255) / 256, 256>>>();  // launch 3
    dim3 grid(NTILES, Bsz);
    for (int it = 0; it < NUM_ITERS; it++) {
        k_fused<<<grid, 256>>>();            // launches 4, 6(=profiled), ...
        k_fin<<<(Bsz * Mm) / (4 * 256), 256>>>();
    }
    k_out<<<8192, 256>>>(out);
}